// round 11
// baseline (speedup 1.0000x reference)
#include <cuda_runtime.h>
#include <cstdint>

// Problem constants
#define HOP     128
#define WINL    512
#define PADW    192
#define NB      32
#define NT      131072
#define NFRM    1024
#define NSTAGE  11

// Tiling: one warp per block, one frame per lane; OLA lives in registers and
// migrates lane-to-lane via shuffle at chunk boundaries.
#define NFB     32
#define BLK_PER_B (NFRM / NFB)             // 32
#define SPAN    ((NFB - 1) * HOP + WINL)   // 4480
#define NROWS   (SPAN / HOP)               // 35
#define SMEMN   (NROWS * (HOP + 1))        // 4515 floats (129-word rows)
#define SMEM_BYTES ((SMEMN + WINL) * sizeof(float))   // 20108 B -> single wave

#define TWO_PI_OVER_WIN 0.012271846303085129f

__device__ __forceinline__ int pidx(int i) { return i + (i >> 7); }

__device__ __forceinline__ float hannw(int n) {
    return 0.5f - 0.5f * __cosf((float)n * TWO_PI_OVER_WIN);
}

__device__ float norm_at(int p) {
    int f_hi = p >> 7; if (f_hi > NFRM - 1) f_hi = NFRM - 1;
    int f_lo = (p >= 384) ? ((p - 384) >> 7) : 0;
    float s = 0.f;
    for (int f = f_lo; f <= f_hi; ++f) s += hannw(p - (f << 7));
    return s;
}

__global__ void halo_zero_kernel(float* __restrict__ out) {
    int b   = blockIdx.y;
    int blk = blockIdx.x + 1;
    int u   = blk * (NFB * HOP) - PADW + (int)threadIdx.x;
    out[(size_t)b * NT + u] = 0.f;
}

// One cascade step: DST[s] = -a1[s]*SRC[s] - a2[s]*DST[s] + in(s),
// in(0)=X (pre-scaled by g), in(s)=SRC[s-1]. 22 independent FMAs.
#define CASCADE(SRC, DST, X)                                          \
    DST##0  = fmaf(na2_0,  DST##0,  fmaf(na1_0,  SRC##0,  (X)));      \
    DST##1  = fmaf(na2_1,  DST##1,  fmaf(na1_1,  SRC##1,  SRC##0));   \
    DST##2  = fmaf(na2_2,  DST##2,  fmaf(na1_2,  SRC##2,  SRC##1));   \
    DST##3  = fmaf(na2_3,  DST##3,  fmaf(na1_3,  SRC##3,  SRC##2));   \
    DST##4  = fmaf(na2_4,  DST##4,  fmaf(na1_4,  SRC##4,  SRC##3));   \
    DST##5  = fmaf(na2_5,  DST##5,  fmaf(na1_5,  SRC##5,  SRC##4));   \
    DST##6  = fmaf(na2_6,  DST##6,  fmaf(na1_6,  SRC##6,  SRC##5));   \
    DST##7  = fmaf(na2_7,  DST##7,  fmaf(na1_7,  SRC##7,  SRC##6));   \
    DST##8  = fmaf(na2_8,  DST##8,  fmaf(na1_8,  SRC##8,  SRC##7));   \
    DST##9  = fmaf(na2_9,  DST##9,  fmaf(na1_9,  SRC##9,  SRC##8));   \
    DST##10 = fmaf(na2_10, DST##10, fmaf(na1_10, SRC##10, SRC##9));

// One chunk: 128 steps, T = 128*C+10+e. Input from lane's staged stream
// (global-span index 128f+t -> in_s[kbase + T + (T>>7)]); all indices
// compile-time after unroll (acc[] MUST never see a runtime index).
// For C==3, steps with T>=512 drain with x=0 (folded at compile time).
#define RUN_CHUNK(C)                                                   \
    _Pragma("unroll")                                                  \
    for (int e = 0; e < 128; e += 2) {                                 \
        {   const int T = 128 * (C) + 10 + e;                          \
            float x = (T < WINL) ? g * in_s[kbase + T + (T >> 7)] : 0.f; \
            CASCADE(pa, pb, x);                                        \
            acc[e] = fmaf(pb10, win_s[128 * (C) + e], acc[e]); }       \
        {   const int T = 128 * (C) + 10 + e + 1;                      \
            float x = (T < WINL) ? g * in_s[kbase + T + (T >> 7)] : 0.f; \
            CASCADE(pb, pa, x);                                        \
            acc[e + 1] = fmaf(pa10, win_s[128 * (C) + e + 1], acc[e + 1]); } \
    }

// Lane 0 retires completed span-block C (positions 128C..128C+127) to gmem,
// then the accumulators migrate one lane down; lane 31 starts a fresh block.
#define DUMP_AND_ROTATE(C) {                                           \
    if (tid == 0) {                                                    \
        if (blk == 0) {                                                \
            _Pragma("unroll")                                          \
            for (int k = 0; k < 128; ++k) {                            \
                int p = 128 * (C) + k;                                 \
                int u = p - PADW;                                      \
                if (u >= 0) outb[u] = acc[k] / norm_at(p);             \
            }                                                          \
        } else {                                                       \
            _Pragma("unroll")                                          \
            for (int k = 0; k < 128; ++k)                              \
                atomicAdd(outb + S0 + 128 * (C) + k - PADW, acc[k] * 0.5f); \
        }                                                              \
    }                                                                  \
    _Pragma("unroll")                                                  \
    for (int k = 0; k < 128; ++k) {                                    \
        float _v = __shfl_down_sync(0xffffffffu, acc[k], 1);           \
        acc[k] = (tid < 31) ? _v : 0.f;                                \
    } }

__global__ __launch_bounds__(NFB, 1) void synth_kernel(const float* __restrict__ ex,
                                                       const float* __restrict__ gain,
                                                       const float* __restrict__ bq,
                                                       float* __restrict__ out) {
    extern __shared__ float sm[];
    float* in_s  = sm;                 // SPAN staged inputs, 129-padded rows
    float* win_s = sm + SMEMN;         // WINL window table

    const int b   = blockIdx.y;
    const int blk = blockIdx.x;
    const int F0  = blk * NFB;
    const int S0  = F0 * HOP;
    const int tid = (int)threadIdx.x;
    const int kbase = tid * (HOP + 1);
    float* outb = out + (size_t)b * NT;

    // ---- Phase A: coalesced staging of the input span (zero-padded edges).
    // Quads never straddle the [0,NT) boundary (all offsets are 4-aligned).
    {
        const float* exb = ex + (size_t)b * NT + (S0 - PADW);
        #pragma unroll 1
        for (int it = 0; it < NROWS; ++it) {
            int e   = it * 128 + tid * 4;
            int pos = S0 - PADW + e;
            float4 v = make_float4(0.f, 0.f, 0.f, 0.f);
            if ((unsigned)pos <= (unsigned)(NT - 4))
                v = *(const float4*)(exb + e);
            int o = e + (e >> 7);
            in_s[o] = v.x; in_s[o+1] = v.y; in_s[o+2] = v.z; in_s[o+3] = v.w;
        }
        for (int i = tid; i < WINL; i += NFB) win_s[i] = hannw(i);
    }

    // ---- Per-frame coefficients (negated for FMA form)
    const int f = F0 + tid;
    const float g = gain[b * NFRM + f];
    const float* bp = bq + (size_t)(b * NFRM + f) * (NSTAGE * 3);
    const float na1_0  = -bp[1],  na2_0  = -bp[2];
    const float na1_1  = -bp[4],  na2_1  = -bp[5];
    const float na1_2  = -bp[7],  na2_2  = -bp[8];
    const float na1_3  = -bp[10], na2_3  = -bp[11];
    const float na1_4  = -bp[13], na2_4  = -bp[14];
    const float na1_5  = -bp[16], na2_5  = -bp[17];
    const float na1_6  = -bp[19], na2_6  = -bp[20];
    const float na1_7  = -bp[22], na2_7  = -bp[23];
    const float na1_8  = -bp[25], na2_8  = -bp[26];
    const float na1_9  = -bp[28], na2_9  = -bp[29];
    const float na1_10 = -bp[31], na2_10 = -bp[32];

    float pa0 = 0.f, pa1 = 0.f, pa2 = 0.f, pa3 = 0.f, pa4 = 0.f, pa5 = 0.f,
          pa6 = 0.f, pa7 = 0.f, pa8 = 0.f, pa9 = 0.f, pa10 = 0.f;
    float pb0 = 0.f, pb1 = 0.f, pb2 = 0.f, pb3 = 0.f, pb4 = 0.f, pb5 = 0.f,
          pb6 = 0.f, pb7 = 0.f, pb8 = 0.f, pb9 = 0.f, pb10 = 0.f;

    float acc[128];
    #pragma unroll
    for (int k = 0; k < 128; ++k) acc[k] = 0.f;

    __syncwarp();   // staged inputs + window visible warp-wide

    // ---- Prologue: t = 0..9 fill the filter pipeline (no output)
    #pragma unroll
    for (int t = 0; t < NSTAGE - 1; t += 2) {
        float x0 = g * in_s[kbase + t];
        float x1 = g * in_s[kbase + t + 1];
        CASCADE(pa, pb, x0);
        CASCADE(pb, pa, x1);
    }

    // ---- Four chunks; acc migrates down one lane per boundary.
    RUN_CHUNK(0)
    DUMP_AND_ROTATE(0)
    RUN_CHUNK(1)
    DUMP_AND_ROTATE(1)
    RUN_CHUNK(2)
    DUMP_AND_ROTATE(2)
    RUN_CHUNK(3)

    // ---- Phase C: lane f now holds the fully-summed span block f+3
    // (positions 128(f+3) .. 128(f+4)-1). Stage through smem (inputs no
    // longer needed) and write coalesced.
    __syncwarp();   // all lanes done reading in_s (chunk-3 reads cross rows)
    #pragma unroll
    for (int k = 0; k < 128; ++k) in_s[kbase + k] = acc[k];
    __syncwarp();

    const bool last = (blk == BLK_PER_B - 1);
    #pragma unroll 4
    for (int i = tid; i < 4096; i += NFB) {
        float v = in_s[pidx(i)];
        int u = S0 + 192 + i;                  // = (S0 + 384 + i) - PADW
        if (i < 3712) {                        // block-interior, norm == 2
            outb[u] = v * 0.5f;
        } else if (!last) {                    // right halo -> pre-zeroed cols
            atomicAdd(outb + u, v * 0.5f);
        } else {                               // batch right edge
            if (u < NT) outb[u] = v / norm_at(S0 + 384 + i);
        }
    }
}

extern "C" void kernel_launch(void* const* d_in, const int* in_sizes, int n_in,
                              void* d_out, int out_size) {
    const float* ex   = (const float*)d_in[0];   // (32, 131072) f32
    const float* gain = (const float*)d_in[1];   // (32, 1024)   f32
    const float* bq   = (const float*)d_in[2];   // (32, 1024, 11, 3) f32
    float* out = (float*)d_out;                  // (32, 131072) f32

    cudaFuncSetAttribute(synth_kernel, cudaFuncAttributeMaxDynamicSharedMemorySize,
                         (int)SMEM_BYTES);

    halo_zero_kernel<<<dim3(BLK_PER_B - 1, NB), 384>>>(out);
    synth_kernel<<<dim3(BLK_PER_B, NB), NFB, SMEM_BYTES>>>(ex, gain, bq, out);
}

// round 12
// speedup vs baseline: 1.2614x; 1.2614x over previous
#include <cuda_runtime.h>
#include <cstdint>

// Problem constants
#define HOP     128
#define WINL    512
#define PADW    192
#define NB      32
#define NT      131072
#define NFRM    1024
#define NSTAGE  11

// Tiling: one warp per block, one frame per lane.
// Input: rows 0..27 staged in smem (lanes 0..23 read them); lanes 24..31 use
// a predicated register/LDG quad stream (R5 path). OLA: 32-slot smem ring with
// diagonal retirement (slot c%32 retired+recycled at each chunk boundary).
#define NFB     32
#define BLK_PER_B (NFRM / NFB)          // 32
#define SROWS   28                      // staged input rows
#define RTHRESH 24                      // lanes >= RTHRESH use the reg path
#define INSZ    (SROWS * (HOP + 1))     // 3612 floats
#define ACCSZ   (32 * (HOP + 1))        // 4128 floats
#define SMEM_BYTES ((INSZ + ACCSZ) * sizeof(float))   // 30960 B -> 7 blocks/SM

#define TWO_PI_OVER_WIN 0.012271846303085129f

__device__ __forceinline__ float hannw(int n) {
    return 0.5f - 0.5f * __cosf((float)n * TWO_PI_OVER_WIN);
}

// OLA normalization at padded global position P.
__device__ float norm_at(int P) {
    int f_hi = P >> 7; if (f_hi > NFRM - 1) f_hi = NFRM - 1;
    int f_lo = (P >= 384) ? ((P - 384) >> 7) : 0;
    float s = 0.f;
    for (int f = f_lo; f <= f_hi; ++f) s += hannw(P - (f << 7));
    return s;
}

__global__ void halo_zero_kernel(float* __restrict__ out) {
    int b   = blockIdx.y;
    int blk = blockIdx.x + 1;
    int u   = blk * (NFB * HOP) - PADW + (int)threadIdx.x;
    out[(size_t)b * NT + u] = 0.f;
}

// One cascade step: DST[s] = -a1[s]*SRC[s] - a2[s]*DST[s] + in(s),
// in(0)=X (pre-scaled by g), in(s)=SRC[s-1]. 22 independent FMAs.
#define CASCADE(SRC, DST, X)                                          \
    DST##0  = fmaf(na2_0,  DST##0,  fmaf(na1_0,  SRC##0,  (X)));      \
    DST##1  = fmaf(na2_1,  DST##1,  fmaf(na1_1,  SRC##1,  SRC##0));   \
    DST##2  = fmaf(na2_2,  DST##2,  fmaf(na1_2,  SRC##2,  SRC##1));   \
    DST##3  = fmaf(na2_3,  DST##3,  fmaf(na1_3,  SRC##3,  SRC##2));   \
    DST##4  = fmaf(na2_4,  DST##4,  fmaf(na1_4,  SRC##4,  SRC##3));   \
    DST##5  = fmaf(na2_5,  DST##5,  fmaf(na1_5,  SRC##5,  SRC##4));   \
    DST##6  = fmaf(na2_6,  DST##6,  fmaf(na1_6,  SRC##6,  SRC##5));   \
    DST##7  = fmaf(na2_7,  DST##7,  fmaf(na1_7,  SRC##7,  SRC##6));   \
    DST##8  = fmaf(na2_8,  DST##8,  fmaf(na1_8,  SRC##8,  SRC##7));   \
    DST##9  = fmaf(na2_9,  DST##9,  fmaf(na1_9,  SRC##9,  SRC##8));   \
    DST##10 = fmaf(na2_10, DST##10, fmaf(na1_10, SRC##10, SRC##9));

// Guarded + predicated quad load (reg-path lanes only issue wavefronts).
__device__ __forceinline__ float4 ld4p(const float* __restrict__ xp, int pos0,
                                       int k, bool pred) {
    int pos = pos0 + 4 * k;
    if (pred && (unsigned)k <= 127u && (unsigned)pos <= (unsigned)(NT - 4))
        return *(const float4*)(xp + 4 * k);
    return make_float4(0.f, 0.f, 0.f, 0.f);
}

// One mainloop step. K compile-time within a 16-step superstep; tb runtime.
// Input: reg lanes take RV (rotating quad fields); smem lanes take staged LDS.
// t >= 512 drains with x = 0. Window via MUFU (no table).
#define STEP(K, PING, PONG, RV) {                                     \
    int _t = tb + (K);                                                 \
    float _xs = in_s[inb + _t + (_t >> 7)];                            \
    float _xv = regp ? (RV) : _xs;                                     \
    _xv = (_t < WINL) ? _xv : 0.f;                                     \
    CASCADE(PING, PONG, g * _xv);                                      \
    float _w = 0.5f - 0.5f * __cosf((float)(_t - 10) * TWO_PI_OVER_WIN); \
    int _aj = accb + 16 * m + (K);                                     \
    acc_s[_aj] = fmaf(PONG##10, _w, acc_s[_aj]); }

__global__ __launch_bounds__(NFB, 1) void synth_kernel(const float* __restrict__ ex,
                                                       const float* __restrict__ gain,
                                                       const float* __restrict__ bq,
                                                       float* __restrict__ out) {
    extern __shared__ float sm[];
    float* in_s  = sm;                 // INSZ floats (28 padded rows)
    float* acc_s = sm + INSZ;          // ACCSZ floats (32 padded ring slots)

    const int b   = blockIdx.y;
    const int blk = blockIdx.x;
    const int F0  = blk * NFB;
    const int S0  = F0 * HOP;
    const int tid = (int)threadIdx.x;
    const bool regp = (tid >= RTHRESH);
    // smem input base; reg lanes clamp to lane 23's row (broadcast, unused)
    const int inb = 129 * (regp ? (RTHRESH - 1) : tid);
    float* outb = out + (size_t)b * NT;

    // Reg-path input stream (same mapping as R5)
    const int   pos0 = S0 + tid * HOP - PADW;
    const float* xp  = ex + (size_t)b * NT + pos0;

    // ---- Phase A: stage input rows 0..27 coalesced; zero the acc ring.
    {
        const float* exb = ex + (size_t)b * NT + (S0 - PADW);
        #pragma unroll 1
        for (int it = 0; it < SROWS; ++it) {
            int e   = it * 128 + tid * 4;
            int pos = S0 - PADW + e;
            float4 v = make_float4(0.f, 0.f, 0.f, 0.f);
            if ((unsigned)pos <= (unsigned)(NT - 4))
                v = *(const float4*)(exb + e);
            int o = 129 * it + tid * 4;
            in_s[o] = v.x; in_s[o+1] = v.y; in_s[o+2] = v.z; in_s[o+3] = v.w;
        }
        for (int i = tid; i < ACCSZ; i += NFB) acc_s[i] = 0.f;
    }

    // Reg-path prologue quads + initial rotation set (predicated loads)
    float4 q0 = ld4p(xp, pos0, 0, regp);
    float4 q1 = ld4p(xp, pos0, 1, regp);
    float4 q2 = ld4p(xp, pos0, 2, regp);
    float4 c0 = ld4p(xp, pos0, 3, regp);
    float4 c1 = ld4p(xp, pos0, 4, regp);
    float4 c2 = ld4p(xp, pos0, 5, regp);
    float4 c3 = ld4p(xp, pos0, 6, regp);

    // ---- Per-frame coefficients (negated for FMA form)
    const int f = F0 + tid;
    const float g = gain[b * NFRM + f];
    const float* bp = bq + (size_t)(b * NFRM + f) * (NSTAGE * 3);
    const float na1_0  = -bp[1],  na2_0  = -bp[2];
    const float na1_1  = -bp[4],  na2_1  = -bp[5];
    const float na1_2  = -bp[7],  na2_2  = -bp[8];
    const float na1_3  = -bp[10], na2_3  = -bp[11];
    const float na1_4  = -bp[13], na2_4  = -bp[14];
    const float na1_5  = -bp[16], na2_5  = -bp[17];
    const float na1_6  = -bp[19], na2_6  = -bp[20];
    const float na1_7  = -bp[22], na2_7  = -bp[23];
    const float na1_8  = -bp[25], na2_8  = -bp[26];
    const float na1_9  = -bp[28], na2_9  = -bp[29];
    const float na1_10 = -bp[31], na2_10 = -bp[32];

    float pa0 = 0.f, pa1 = 0.f, pa2 = 0.f, pa3 = 0.f, pa4 = 0.f, pa5 = 0.f,
          pa6 = 0.f, pa7 = 0.f, pa8 = 0.f, pa9 = 0.f, pa10 = 0.f;
    float pb0 = 0.f, pb1 = 0.f, pb2 = 0.f, pb3 = 0.f, pb4 = 0.f, pb5 = 0.f,
          pb6 = 0.f, pb7 = 0.f, pb8 = 0.f, pb9 = 0.f, pb10 = 0.f;

    __syncwarp();   // staging + acc zero visible warp-wide

    // ---- Prologue: t = 0..9 fill the filter pipeline (no output)
    #define PX(QF, T) (regp ? (QF) : in_s[inb + (T)])
    CASCADE(pa, pb, g * PX(q0.x, 0)); CASCADE(pb, pa, g * PX(q0.y, 1));
    CASCADE(pa, pb, g * PX(q0.z, 2)); CASCADE(pb, pa, g * PX(q0.w, 3));
    CASCADE(pa, pb, g * PX(q1.x, 4)); CASCADE(pb, pa, g * PX(q1.y, 5));
    CASCADE(pa, pb, g * PX(q1.z, 6)); CASCADE(pb, pa, g * PX(q1.w, 7));
    CASCADE(pa, pb, g * PX(q2.x, 8)); CASCADE(pb, pa, g * PX(q2.y, 9));
    float x0 = q2.z, x1 = q2.w;        // reg-path carries: t = 10, 11

    // ---- Mainloop: 4 chunks x 8 supersteps x 16 steps. Chunk c: outputs
    // j in [128c, 128c+128), steps t = j + 10. Lane f accumulates into ring
    // slot (f+c)&31 == span row f+c. Boundary: retire+recycle slot c.
    #pragma unroll 1
    for (int c = 0; c < 4; ++c) {
        const int accb = 129 * ((tid + c) & 31);
        #pragma unroll 1
        for (int m = 0; m < 8; ++m) {
            const int tb = 128 * c + 10 + 16 * m;
            const int kq = 3 + 32 * c + 4 * (m + 1);    // next superstep quads
            float4 n0 = ld4p(xp, pos0, kq,     regp);
            float4 n1 = ld4p(xp, pos0, kq + 1, regp);
            float4 n2 = ld4p(xp, pos0, kq + 2, regp);
            float4 n3 = ld4p(xp, pos0, kq + 3, regp);
            STEP(0,  pa, pb, x0)   STEP(1,  pb, pa, x1)
            STEP(2,  pa, pb, c0.x) STEP(3,  pb, pa, c0.y)
            STEP(4,  pa, pb, c0.z) STEP(5,  pb, pa, c0.w)
            STEP(6,  pa, pb, c1.x) STEP(7,  pb, pa, c1.y)
            STEP(8,  pa, pb, c1.z) STEP(9,  pb, pa, c1.w)
            STEP(10, pa, pb, c2.x) STEP(11, pb, pa, c2.y)
            STEP(12, pa, pb, c2.z) STEP(13, pb, pa, c2.w)
            STEP(14, pa, pb, c3.x) STEP(15, pb, pa, c3.y)
            x0 = c3.z; x1 = c3.w;
            c0 = n0; c1 = n1; c2 = n2; c3 = n3;
        }
        __syncwarp();
        if (c < 3) {
            // Retire span row c (ring slot c) cooperatively, then recycle it
            // (it becomes row c+32, written by lane 31 next chunk).
            const int sb = 129 * c;
            #pragma unroll
            for (int k2 = 0; k2 < 4; ++k2) {
                int j = tid + 32 * k2;
                float v = acc_s[sb + j];
                int p = 128 * c + j;           // span position (< 384)
                int u = S0 + p - PADW;
                if (blk == 0) { if (u >= 0) outb[u] = v / norm_at(p); }
                else atomicAdd(outb + u, v * 0.5f);
                acc_s[sb + j] = 0.f;
            }
            __syncwarp();
        }
    }

    // ---- Phase C: retire remaining rows 3..34 (all complete after chunk 3).
    #pragma unroll 1
    for (int B = 3; B < 35; ++B) {
        const int sb = 129 * (B & 31);
        #pragma unroll
        for (int k2 = 0; k2 < 4; ++k2) {
            int j = tid + 32 * k2;
            float v = acc_s[sb + j];
            int p = 128 * B + j;
            int u = S0 + p - PADW;
            if (B < 32) {
                outb[u] = v * 0.5f;                       // interior, norm==2
            } else if (blk != BLK_PER_B - 1) {
                atomicAdd(outb + u, v * 0.5f);            // right halo
            } else {
                if (u < NT) outb[u] = v / norm_at(S0 + p); // batch right edge
            }
        }
    }
}

extern "C" void kernel_launch(void* const* d_in, const int* in_sizes, int n_in,
                              void* d_out, int out_size) {
    const float* ex   = (const float*)d_in[0];   // (32, 131072) f32
    const float* gain = (const float*)d_in[1];   // (32, 1024)   f32
    const float* bq   = (const float*)d_in[2];   // (32, 1024, 11, 3) f32
    float* out = (float*)d_out;                  // (32, 131072) f32

    cudaFuncSetAttribute(synth_kernel, cudaFuncAttributeMaxDynamicSharedMemorySize,
                         (int)SMEM_BYTES);

    halo_zero_kernel<<<dim3(BLK_PER_B - 1, NB), 384>>>(out);
    synth_kernel<<<dim3(BLK_PER_B, NB), NFB, SMEM_BYTES>>>(ex, gain, bq, out);
}

// round 14
// speedup vs baseline: 1.3187x; 1.0454x over previous
#include <cuda_runtime.h>
#include <cstdint>

// Problem constants
#define HOP     128
#define WINL    512
#define PADW    192
#define NB      32
#define NT      131072
#define NFRM    1024
#define NSTAGE  11

// Tiling: one warp per block, one frame per lane.
// Input: rows 0..27 staged in smem (lanes 0..23); lanes 24..31 use a
// predicated register/LDG quad stream. OLA: 32-slot smem ring with diagonal
// retirement. Window: 257-entry mirrored hann half-table.
#define NFB     32
#define BLK_PER_B (NFRM / NFB)          // 32
#define SROWS   28                      // staged input rows
#define RTHRESH 24                      // lanes >= RTHRESH use the reg path
#define INSZ    (SROWS * (HOP + 1))     // 3612 floats
#define ACCSZ   (32 * (HOP + 1))        // 4128 floats
#define WSZ     257
#define SMEM_BYTES ((INSZ + ACCSZ + WSZ) * sizeof(float))   // 31988 B -> 7 blocks/SM

#define TWO_PI_OVER_WIN 0.012271846303085129f

__device__ __forceinline__ float hannw(int n) {
    return 0.5f - 0.5f * __cosf((float)n * TWO_PI_OVER_WIN);
}

// OLA normalization at padded global position P.
__device__ float norm_at(int P) {
    int f_hi = P >> 7; if (f_hi > NFRM - 1) f_hi = NFRM - 1;
    int f_lo = (P >= 384) ? ((P - 384) >> 7) : 0;
    float s = 0.f;
    for (int f = f_lo; f <= f_hi; ++f) s += hannw(P - (f << 7));
    return s;
}

__global__ void halo_zero_kernel(float* __restrict__ out) {
    int b   = blockIdx.y;
    int blk = blockIdx.x + 1;
    int u   = blk * (NFB * HOP) - PADW + (int)threadIdx.x;
    out[(size_t)b * NT + u] = 0.f;
}

// One cascade step: DST[s] = -a1[s]*SRC[s] - a2[s]*DST[s] + in(s),
// in(0)=X, in(s)=SRC[s-1]. 22 independent FMAs.
#define CASCADE(SRC, DST, X)                                          \
    DST##0  = fmaf(na2_0,  DST##0,  fmaf(na1_0,  SRC##0,  (X)));      \
    DST##1  = fmaf(na2_1,  DST##1,  fmaf(na1_1,  SRC##1,  SRC##0));   \
    DST##2  = fmaf(na2_2,  DST##2,  fmaf(na1_2,  SRC##2,  SRC##1));   \
    DST##3  = fmaf(na2_3,  DST##3,  fmaf(na1_3,  SRC##3,  SRC##2));   \
    DST##4  = fmaf(na2_4,  DST##4,  fmaf(na1_4,  SRC##4,  SRC##3));   \
    DST##5  = fmaf(na2_5,  DST##5,  fmaf(na1_5,  SRC##5,  SRC##4));   \
    DST##6  = fmaf(na2_6,  DST##6,  fmaf(na1_6,  SRC##6,  SRC##5));   \
    DST##7  = fmaf(na2_7,  DST##7,  fmaf(na1_7,  SRC##7,  SRC##6));   \
    DST##8  = fmaf(na2_8,  DST##8,  fmaf(na1_8,  SRC##8,  SRC##7));   \
    DST##9  = fmaf(na2_9,  DST##9,  fmaf(na1_9,  SRC##9,  SRC##8));   \
    DST##10 = fmaf(na2_10, DST##10, fmaf(na1_10, SRC##10, SRC##9));

// Guarded + predicated quad load (only reg-path lanes issue wavefronts).
__device__ __forceinline__ float4 ld4p(const float* __restrict__ xp, int pos0,
                                       int k, bool pred) {
    int pos = pos0 + 4 * k;
    if (pred && (unsigned)k <= 127u && (unsigned)pos <= (unsigned)(NT - 4))
        return *(const float4*)(xp + 4 * k);
    return make_float4(0.f, 0.f, 0.f, 0.f);
}

// Steps with immediate offsets off per-superstep base pointers ipt/apt/wpt.
// A = ascending window (chunks 0,1), D = descending/mirrored (chunks 2,3).
// *2 variants: input index bumped by +1 (row crossing inside peeled m=7).
// G variant: drain guard (x=0 for t>=512, chunk-3 peel).
#define STEPA(K, PING, PONG, RV) {                                    \
    float _x = g * (regp ? (RV) : ipt[(K)]);                          \
    CASCADE(PING, PONG, _x);                                          \
    apt[(K)] = fmaf(PONG##10, wpt[(K)], apt[(K)]); }
#define STEPA2(K, PING, PONG, RV) {                                   \
    float _x = g * (regp ? (RV) : ipt[(K) + 1]);                      \
    CASCADE(PING, PONG, _x);                                          \
    apt[(K)] = fmaf(PONG##10, wpt[(K)], apt[(K)]); }
#define STEPD(K, PING, PONG, RV) {                                    \
    float _x = g * (regp ? (RV) : ipt[(K)]);                          \
    CASCADE(PING, PONG, _x);                                          \
    apt[(K)] = fmaf(PONG##10, wpt[-(K)], apt[(K)]); }
#define STEPD2G(K, PING, PONG, RV) {                                  \
    float _x = g * (regp ? (RV) : ipt[(K) + 1]);                      \
    _x = (tb + (K) < WINL) ? _x : 0.f;                                \
    CASCADE(PING, PONG, _x);                                          \
    apt[(K)] = fmaf(PONG##10, wpt[-(K)], apt[(K)]); }

// 16 steps of a full superstep (inputs: carries x0,x1 then quads c0..c3).
#define SS16(S, S2)                                                    \
    S(0,  pa, pb, x0)    S(1,  pb, pa, x1)                             \
    S(2,  pa, pb, c0.x)  S(3,  pb, pa, c0.y)                           \
    S(4,  pa, pb, c0.z)  S(5,  pb, pa, c0.w)                           \
    S2(6, pa, pb, c1.x)  S2(7, pb, pa, c1.y)                           \
    S2(8, pa, pb, c1.z)  S2(9, pb, pa, c1.w)                           \
    S2(10, pa, pb, c2.x) S2(11, pb, pa, c2.y)                          \
    S2(12, pa, pb, c2.z) S2(13, pb, pa, c2.w)                          \
    S2(14, pa, pb, c3.x) S2(15, pb, pa, c3.y)

#define PREFETCH(KQ)                                                   \
    float4 n0 = ld4p(xp, pos0, (KQ),     regp);                        \
    float4 n1 = ld4p(xp, pos0, (KQ) + 1, regp);                        \
    float4 n2 = ld4p(xp, pos0, (KQ) + 2, regp);                        \
    float4 n3 = ld4p(xp, pos0, (KQ) + 3, regp);

#define ROTATE()                                                       \
    x0 = c3.z; x1 = c3.w; c0 = n0; c1 = n1; c2 = n2; c3 = n3;

// Retire ring slot C holding span row C, then recycle it (zeroed).
#define RETIRE_EARLY(C) {                                              \
    const int sb = 129 * (C);                                          \
    _Pragma("unroll")                                                  \
    for (int k2 = 0; k2 < 4; ++k2) {                                   \
        int j = tid + 32 * k2;                                         \
        float v = acc_s[sb + j];                                       \
        int p = 128 * (C) + j;                                         \
        int u = S0 + p - PADW;                                         \
        if (blk == 0) { if (u >= 0) outb[u] = v / norm_at(p); }        \
        else atomicAdd(outb + u, v * 0.5f);                            \
        acc_s[sb + j] = 0.f;                                           \
    } }

__global__ __launch_bounds__(NFB, 1) void synth_kernel(const float* __restrict__ ex,
                                                       const float* __restrict__ gain,
                                                       const float* __restrict__ bq,
                                                       float* __restrict__ out) {
    extern __shared__ float sm[];
    float* in_s  = sm;                 // 28 padded input rows
    float* acc_s = sm + INSZ;          // 32 padded ring slots
    float* win_s = sm + INSZ + ACCSZ;  // 257-entry hann half-table

    const int b   = blockIdx.y;
    const int blk = blockIdx.x;
    const int F0  = blk * NFB;
    const int S0  = F0 * HOP;
    const int tid = (int)threadIdx.x;
    const bool regp = (tid >= RTHRESH);
    const int inb = 129 * (regp ? (RTHRESH - 1) : tid);
    float* outb = out + (size_t)b * NT;

    const int   pos0 = S0 + tid * HOP - PADW;
    const float* xp  = ex + (size_t)b * NT + pos0;

    // ---- Phase A: stage input rows coalesced; zero acc ring; window table.
    {
        const float* exb = ex + (size_t)b * NT + (S0 - PADW);
        #pragma unroll 1
        for (int it = 0; it < SROWS; ++it) {
            int e   = it * 128 + tid * 4;
            int pos = S0 - PADW + e;
            float4 v = make_float4(0.f, 0.f, 0.f, 0.f);
            if ((unsigned)pos <= (unsigned)(NT - 4))
                v = *(const float4*)(exb + e);
            int o = 129 * it + tid * 4;
            in_s[o] = v.x; in_s[o+1] = v.y; in_s[o+2] = v.z; in_s[o+3] = v.w;
        }
        for (int i = tid; i < ACCSZ; i += NFB) acc_s[i] = 0.f;
        for (int i = tid; i < WSZ; i += NFB) win_s[i] = hannw(i);
    }

    // Reg-path prologue + initial rotation quads
    float4 q0 = ld4p(xp, pos0, 0, regp);
    float4 q1 = ld4p(xp, pos0, 1, regp);
    float4 q2 = ld4p(xp, pos0, 2, regp);
    float4 c0 = ld4p(xp, pos0, 3, regp);
    float4 c1 = ld4p(xp, pos0, 4, regp);
    float4 c2 = ld4p(xp, pos0, 5, regp);
    float4 c3 = ld4p(xp, pos0, 6, regp);

    // ---- Per-frame coefficients (negated for FMA form)
    const int f = F0 + tid;
    const float g = gain[b * NFRM + f];
    const float* bp = bq + (size_t)(b * NFRM + f) * (NSTAGE * 3);
    const float na1_0  = -bp[1],  na2_0  = -bp[2];
    const float na1_1  = -bp[4],  na2_1  = -bp[5];
    const float na1_2  = -bp[7],  na2_2  = -bp[8];
    const float na1_3  = -bp[10], na2_3  = -bp[11];
    const float na1_4  = -bp[13], na2_4  = -bp[14];
    const float na1_5  = -bp[16], na2_5  = -bp[17];
    const float na1_6  = -bp[19], na2_6  = -bp[20];
    const float na1_7  = -bp[22], na2_7  = -bp[23];
    const float na1_8  = -bp[25], na2_8  = -bp[26];
    const float na1_9  = -bp[28], na2_9  = -bp[29];
    const float na1_10 = -bp[31], na2_10 = -bp[32];

    float pa0 = 0.f, pa1 = 0.f, pa2 = 0.f, pa3 = 0.f, pa4 = 0.f, pa5 = 0.f,
          pa6 = 0.f, pa7 = 0.f, pa8 = 0.f, pa9 = 0.f, pa10 = 0.f;
    float pb0 = 0.f, pb1 = 0.f, pb2 = 0.f, pb3 = 0.f, pb4 = 0.f, pb5 = 0.f,
          pb6 = 0.f, pb7 = 0.f, pb8 = 0.f, pb9 = 0.f, pb10 = 0.f;

    __syncwarp();   // staging + acc zero + window visible

    // ---- Prologue: t = 0..9 fill the filter pipeline (no output)
    #define PX(QF, T) (g * (regp ? (QF) : in_s[inb + (T)]))
    CASCADE(pa, pb, PX(q0.x, 0)); CASCADE(pb, pa, PX(q0.y, 1));
    CASCADE(pa, pb, PX(q0.z, 2)); CASCADE(pb, pa, PX(q0.w, 3));
    CASCADE(pa, pb, PX(q1.x, 4)); CASCADE(pb, pa, PX(q1.y, 5));
    CASCADE(pa, pb, PX(q1.z, 6)); CASCADE(pb, pa, PX(q1.w, 7));
    CASCADE(pa, pb, PX(q2.x, 8)); CASCADE(pb, pa, PX(q2.y, 9));
    float x0 = q2.z, x1 = q2.w;        // reg-path carries: t = 10, 11

    // ---- Chunks 0,1 (ascending window). Supersteps m=0..6 uniform; m=7
    // peeled (input row-crossing at K=6: ipt[K+1]).
    #pragma unroll 1
    for (int c = 0; c < 2; ++c) {
        const int accb = 129 * ((tid + c) & 31);
        #pragma unroll 1
        for (int m = 0; m < 7; ++m) {
            const int tb = 128 * c + 10 + 16 * m;
            const float* ipt = in_s + inb + tb + c;
            float*       apt = acc_s + accb + 16 * m;
            const float* wpt = win_s + 128 * c + 16 * m;
            PREFETCH(3 + 32 * c + 4 * (m + 1))
            SS16(STEPA, STEPA)
            ROTATE()
        }
        {   // m = 7
            const float* ipt = in_s + inb + 128 * c + 122 + c;
            float*       apt = acc_s + accb + 112;
            const float* wpt = win_s + 128 * c + 112;
            PREFETCH(35 + 32 * c)
            SS16(STEPA, STEPA2)
            ROTATE()
        }
        __syncwarp();
        RETIRE_EARLY(c)
        __syncwarp();
    }

    // ---- Chunks 2,3 (mirrored window). Chunk-3 peel drains t>=512 via the
    // tb+K < WINL predicate in STEPD2G.
    #pragma unroll 1
    for (int c = 2; c < 4; ++c) {
        const int accb = 129 * ((tid + c) & 31);
        #pragma unroll 1
        for (int m = 0; m < 7; ++m) {
            const int tb = 128 * c + 10 + 16 * m;
            const float* ipt = in_s + inb + tb + c;
            float*       apt = acc_s + accb + 16 * m;
            const float* wpt = win_s + (512 - 128 * c) - 16 * m;
            PREFETCH(3 + 32 * c + 4 * (m + 1))
            SS16(STEPD, STEPD)
            ROTATE()
        }
        {   // m = 7
            const int tb = 128 * c + 122;
            const float* ipt = in_s + inb + tb + c;
            float*       apt = acc_s + accb + 112;
            const float* wpt = win_s + (512 - 128 * c) - 112;
            PREFETCH(35 + 32 * c)
            SS16(STEPD, STEPD2G)
            ROTATE()
        }
        __syncwarp();
        if (c == 2) { RETIRE_EARLY(2) __syncwarp(); }
    }

    // ---- Phase C: retire remaining rows 3..34.
    #pragma unroll 1
    for (int B = 3; B < 35; ++B) {
        const int sb = 129 * (B & 31);
        #pragma unroll
        for (int k2 = 0; k2 < 4; ++k2) {
            int j = tid + 32 * k2;
            float v = acc_s[sb + j];
            int p = 128 * B + j;
            int u = S0 + p - PADW;
            if (B < 32) {
                outb[u] = v * 0.5f;                        // interior, norm==2
            } else if (blk != BLK_PER_B - 1) {
                atomicAdd(outb + u, v * 0.5f);             // right halo
            } else {
                if (u < NT) outb[u] = v / norm_at(S0 + p); // batch right edge
            }
        }
    }
}

extern "C" void kernel_launch(void* const* d_in, const int* in_sizes, int n_in,
                              void* d_out, int out_size) {
    const float* ex   = (const float*)d_in[0];   // (32, 131072) f32
    const float* gain = (const float*)d_in[1];   // (32, 1024)   f32
    const float* bq   = (const float*)d_in[2];   // (32, 1024, 11, 3) f32
    float* out = (float*)d_out;                  // (32, 131072) f32

    cudaFuncSetAttribute(synth_kernel, cudaFuncAttributeMaxDynamicSharedMemorySize,
                         (int)SMEM_BYTES);

    halo_zero_kernel<<<dim3(BLK_PER_B - 1, NB), 384>>>(out);
    synth_kernel<<<dim3(BLK_PER_B, NB), NFB, SMEM_BYTES>>>(ex, gain, bq, out);
}

// round 16
// speedup vs baseline: 1.3814x; 1.0476x over previous
#include <cuda_runtime.h>
#include <cstdint>

// Problem constants
#define HOP     128
#define WINL    512
#define PADW    192
#define NB      32
#define NT      131072
#define NFRM    1024
#define NSTAGE  11

// Tiling: one warp per block, one frame per lane.
// Input: rows 0..27 staged in smem (lanes 0..23); lanes 24..31 use a
// predicated register/LDG quad stream. OLA: 32-slot smem ring with diagonal
// retirement. Window: 257-entry mirrored hann half-table.
// Supersteps gather ALL operands (input/window/acc) into registers first,
// then run a pure FMA+STS burst (no loads inside the compute phase).
#define NFB     32
#define BLK_PER_B (NFRM / NFB)          // 32
#define SROWS   28                      // staged input rows
#define RTHRESH 24                      // lanes >= RTHRESH use the reg path
#define INSZ    (SROWS * (HOP + 1))     // 3612 floats
#define ACCSZ   (32 * (HOP + 1))        // 4128 floats
#define WSZ     257
#define SMEM_BYTES ((INSZ + ACCSZ + WSZ) * sizeof(float))   // 31988 B -> 7 blocks/SM

#define TWO_PI_OVER_WIN 0.012271846303085129f

__device__ __forceinline__ float hannw(int n) {
    return 0.5f - 0.5f * __cosf((float)n * TWO_PI_OVER_WIN);
}

// OLA normalization at padded global position P.
__device__ float norm_at(int P) {
    int f_hi = P >> 7; if (f_hi > NFRM - 1) f_hi = NFRM - 1;
    int f_lo = (P >= 384) ? ((P - 384) >> 7) : 0;
    float s = 0.f;
    for (int f = f_lo; f <= f_hi; ++f) s += hannw(P - (f << 7));
    return s;
}

__global__ void halo_zero_kernel(float* __restrict__ out) {
    int b   = blockIdx.y;
    int blk = blockIdx.x + 1;
    int u   = blk * (NFB * HOP) - PADW + (int)threadIdx.x;
    out[(size_t)b * NT + u] = 0.f;
}

// One cascade step: DST[s] = -a1[s]*SRC[s] - a2[s]*DST[s] + in(s),
// in(0)=X, in(s)=SRC[s-1]. 22 independent FMAs.
#define CASCADE(SRC, DST, X)                                          \
    DST##0  = fmaf(na2_0,  DST##0,  fmaf(na1_0,  SRC##0,  (X)));      \
    DST##1  = fmaf(na2_1,  DST##1,  fmaf(na1_1,  SRC##1,  SRC##0));   \
    DST##2  = fmaf(na2_2,  DST##2,  fmaf(na1_2,  SRC##2,  SRC##1));   \
    DST##3  = fmaf(na2_3,  DST##3,  fmaf(na1_3,  SRC##3,  SRC##2));   \
    DST##4  = fmaf(na2_4,  DST##4,  fmaf(na1_4,  SRC##4,  SRC##3));   \
    DST##5  = fmaf(na2_5,  DST##5,  fmaf(na1_5,  SRC##5,  SRC##4));   \
    DST##6  = fmaf(na2_6,  DST##6,  fmaf(na1_6,  SRC##6,  SRC##5));   \
    DST##7  = fmaf(na2_7,  DST##7,  fmaf(na1_7,  SRC##7,  SRC##6));   \
    DST##8  = fmaf(na2_8,  DST##8,  fmaf(na1_8,  SRC##8,  SRC##7));   \
    DST##9  = fmaf(na2_9,  DST##9,  fmaf(na1_9,  SRC##9,  SRC##8));   \
    DST##10 = fmaf(na2_10, DST##10, fmaf(na1_10, SRC##10, SRC##9));

// Guarded + predicated quad load (only reg-path lanes issue wavefronts).
__device__ __forceinline__ float4 ld4p(const float* __restrict__ xp, int pos0,
                                       int k, bool pred) {
    int pos = pos0 + 4 * k;
    if (pred && (unsigned)k <= 127u && (unsigned)pos <= (unsigned)(NT - 4))
        return *(const float4*)(xp + 4 * k);
    return make_float4(0.f, 0.f, 0.f, 0.f);
}

// ---- Operand gather (all compile-time indices -> registers) ----
// Inputs, gain folded. B = +1 row-crossing bump for K>=6 (peeled m=7).
#define FILL_X(B) {                                                    \
    xin[0] = g * (regp ? x0   : ipt[0]);                               \
    xin[1] = g * (regp ? x1   : ipt[1]);                               \
    xin[2] = g * (regp ? c0.x : ipt[2]);                               \
    xin[3] = g * (regp ? c0.y : ipt[3]);                               \
    xin[4] = g * (regp ? c0.z : ipt[4]);                               \
    xin[5] = g * (regp ? c0.w : ipt[5]);                               \
    xin[6] = g * (regp ? c1.x : ipt[6 + (B)]);                         \
    xin[7] = g * (regp ? c1.y : ipt[7 + (B)]);                         \
    xin[8] = g * (regp ? c1.z : ipt[8 + (B)]);                         \
    xin[9] = g * (regp ? c1.w : ipt[9 + (B)]);                         \
    xin[10] = g * (regp ? c2.x : ipt[10 + (B)]);                       \
    xin[11] = g * (regp ? c2.y : ipt[11 + (B)]);                       \
    xin[12] = g * (regp ? c2.z : ipt[12 + (B)]);                       \
    xin[13] = g * (regp ? c2.w : ipt[13 + (B)]);                       \
    xin[14] = g * (regp ? c3.x : ipt[14 + (B)]);                       \
    xin[15] = g * (regp ? c3.y : ipt[15 + (B)]); }

// Chunk-3 m=7 drain: t = 506..521, inputs valid only for K < 6 (t < 512).
#define FILL_X_DRAIN() {                                               \
    xin[0] = g * (regp ? x0   : ipt[0]);                               \
    xin[1] = g * (regp ? x1   : ipt[1]);                               \
    xin[2] = g * (regp ? c0.x : ipt[2]);                               \
    xin[3] = g * (regp ? c0.y : ipt[3]);                               \
    xin[4] = g * (regp ? c0.z : ipt[4]);                               \
    xin[5] = g * (regp ? c0.w : ipt[5]);                               \
    _Pragma("unroll")                                                  \
    for (int k = 6; k < 16; ++k) xin[k] = 0.f; }

#define FILL_W_A()  { _Pragma("unroll") for (int k = 0; k < 16; ++k) wv[k] = wq[k]; }
#define FILL_W_D()  { _Pragma("unroll") for (int k = 0; k < 16; ++k) wv[k] = wq[15 - k]; }
#define FILL_A()    { _Pragma("unroll") for (int k = 0; k < 16; ++k) av[k] = apt[k]; }

// ---- Compute bursts: no loads inside ----
#define RUN2_ST(K)                                                     \
    CASCADE(pa, pb, xin[(K)]);     apt[(K)]     = pb10 * wv[(K)];      \
    CASCADE(pb, pa, xin[(K) + 1]); apt[(K) + 1] = pa10 * wv[(K) + 1];
#define RUN16_ST()                                                     \
    RUN2_ST(0) RUN2_ST(2) RUN2_ST(4) RUN2_ST(6)                        \
    RUN2_ST(8) RUN2_ST(10) RUN2_ST(12) RUN2_ST(14)

#define RUN2_ACC(K)                                                    \
    CASCADE(pa, pb, xin[(K)]);                                         \
    apt[(K)]     = fmaf(pb10, wv[(K)],     av[(K)]);                   \
    CASCADE(pb, pa, xin[(K) + 1]);                                     \
    apt[(K) + 1] = fmaf(pa10, wv[(K) + 1], av[(K) + 1]);
#define RUN16_ACC()                                                    \
    RUN2_ACC(0) RUN2_ACC(2) RUN2_ACC(4) RUN2_ACC(6)                    \
    RUN2_ACC(8) RUN2_ACC(10) RUN2_ACC(12) RUN2_ACC(14)

#define PREFETCH(KQ)                                                   \
    float4 n0 = ld4p(xp, pos0, (KQ),     regp);                        \
    float4 n1 = ld4p(xp, pos0, (KQ) + 1, regp);                        \
    float4 n2 = ld4p(xp, pos0, (KQ) + 2, regp);                        \
    float4 n3 = ld4p(xp, pos0, (KQ) + 3, regp);

#define ROTATE()                                                       \
    x0 = c3.z; x1 = c3.w; c0 = n0; c1 = n1; c2 = n2; c3 = n3;

// Retire ring slot C holding span row C, then recycle it (zeroed).
#define RETIRE_EARLY(C) {                                              \
    const int sb = 129 * (C);                                          \
    _Pragma("unroll")                                                  \
    for (int k2 = 0; k2 < 4; ++k2) {                                   \
        int j = tid + 32 * k2;                                         \
        float v = acc_s[sb + j];                                       \
        int p = 128 * (C) + j;                                         \
        int u = S0 + p - PADW;                                         \
        if (blk == 0) { if (u >= 0) outb[u] = v / norm_at(p); }        \
        else atomicAdd(outb + u, v * 0.5f);                            \
        acc_s[sb + j] = 0.f;                                           \
    } }

__global__ __launch_bounds__(NFB, 1) void synth_kernel(const float* __restrict__ ex,
                                                       const float* __restrict__ gain,
                                                       const float* __restrict__ bq,
                                                       float* __restrict__ out) {
    extern __shared__ float sm[];
    float* in_s  = sm;                 // 28 padded input rows
    float* acc_s = sm + INSZ;          // 32 padded ring slots
    float* win_s = sm + INSZ + ACCSZ;  // 257-entry hann half-table

    const int b   = blockIdx.y;
    const int blk = blockIdx.x;
    const int F0  = blk * NFB;
    const int S0  = F0 * HOP;
    const int tid = (int)threadIdx.x;
    const bool regp = (tid >= RTHRESH);
    const int inb = 129 * (regp ? (RTHRESH - 1) : tid);
    float* outb = out + (size_t)b * NT;

    const int   pos0 = S0 + tid * HOP - PADW;
    const float* xp  = ex + (size_t)b * NT + pos0;

    // ---- Phase A: stage input rows coalesced; window table. (No acc zeroing:
    // chunk 0 pure-stores all 128 entries of every ring slot.)
    {
        const float* exb = ex + (size_t)b * NT + (S0 - PADW);
        #pragma unroll 1
        for (int it = 0; it < SROWS; ++it) {
            int e   = it * 128 + tid * 4;
            int pos = S0 - PADW + e;
            float4 v = make_float4(0.f, 0.f, 0.f, 0.f);
            if ((unsigned)pos <= (unsigned)(NT - 4))
                v = *(const float4*)(exb + e);
            int o = 129 * it + tid * 4;
            in_s[o] = v.x; in_s[o+1] = v.y; in_s[o+2] = v.z; in_s[o+3] = v.w;
        }
        for (int i = tid; i < WSZ; i += NFB) win_s[i] = hannw(i);
    }

    // Reg-path prologue + initial rotation quads
    float4 q0 = ld4p(xp, pos0, 0, regp);
    float4 q1 = ld4p(xp, pos0, 1, regp);
    float4 q2 = ld4p(xp, pos0, 2, regp);
    float4 c0 = ld4p(xp, pos0, 3, regp);
    float4 c1 = ld4p(xp, pos0, 4, regp);
    float4 c2 = ld4p(xp, pos0, 5, regp);
    float4 c3 = ld4p(xp, pos0, 6, regp);

    // ---- Per-frame coefficients (negated for FMA form)
    const int f = F0 + tid;
    const float g = gain[b * NFRM + f];
    const float* bp = bq + (size_t)(b * NFRM + f) * (NSTAGE * 3);
    const float na1_0  = -bp[1],  na2_0  = -bp[2];
    const float na1_1  = -bp[4],  na2_1  = -bp[5];
    const float na1_2  = -bp[7],  na2_2  = -bp[8];
    const float na1_3  = -bp[10], na2_3  = -bp[11];
    const float na1_4  = -bp[13], na2_4  = -bp[14];
    const float na1_5  = -bp[16], na2_5  = -bp[17];
    const float na1_6  = -bp[19], na2_6  = -bp[20];
    const float na1_7  = -bp[22], na2_7  = -bp[23];
    const float na1_8  = -bp[25], na2_8  = -bp[26];
    const float na1_9  = -bp[28], na2_9  = -bp[29];
    const float na1_10 = -bp[31], na2_10 = -bp[32];

    float pa0 = 0.f, pa1 = 0.f, pa2 = 0.f, pa3 = 0.f, pa4 = 0.f, pa5 = 0.f,
          pa6 = 0.f, pa7 = 0.f, pa8 = 0.f, pa9 = 0.f, pa10 = 0.f;
    float pb0 = 0.f, pb1 = 0.f, pb2 = 0.f, pb3 = 0.f, pb4 = 0.f, pb5 = 0.f,
          pb6 = 0.f, pb7 = 0.f, pb8 = 0.f, pb9 = 0.f, pb10 = 0.f;

    // Operand arrays (all indices compile-time -> registers)
    float xin[16], wv[16], av[16];

    __syncwarp();   // staging + window visible

    // ---- Prologue: t = 0..9 fill the filter pipeline (no output)
    #define PX(QF, T) (g * (regp ? (QF) : in_s[inb + (T)]))
    CASCADE(pa, pb, PX(q0.x, 0)); CASCADE(pb, pa, PX(q0.y, 1));
    CASCADE(pa, pb, PX(q0.z, 2)); CASCADE(pb, pa, PX(q0.w, 3));
    CASCADE(pa, pb, PX(q1.x, 4)); CASCADE(pb, pa, PX(q1.y, 5));
    CASCADE(pa, pb, PX(q1.z, 6)); CASCADE(pb, pa, PX(q1.w, 7));
    CASCADE(pa, pb, PX(q2.x, 8)); CASCADE(pb, pa, PX(q2.y, 9));
    float x0 = q2.z, x1 = q2.w;        // reg-path carries: t = 10, 11

    // ---- Chunk 0 (ascending window, PURE STORES — first write of each slot)
    {
        const int accb = 129 * tid;
        #pragma unroll 1
        for (int m = 0; m < 7; ++m) {
            const float* ipt = in_s + inb + 10 + 16 * m;
            float*       apt = acc_s + accb + 16 * m;
            const float* wq  = win_s + 16 * m;
            PREFETCH(3 + 4 * (m + 1))
            FILL_X(0) FILL_W_A()
            ROTATE()
            RUN16_ST()
        }
        {   // m = 7 (input row-crossing at K>=6)
            const float* ipt = in_s + inb + 122;
            float*       apt = acc_s + accb + 112;
            const float* wq  = win_s + 112;
            PREFETCH(35)
            FILL_X(1) FILL_W_A()
            ROTATE()
            RUN16_ST()
        }
        __syncwarp();
        RETIRE_EARLY(0)
        __syncwarp();
    }

    // ---- Chunk 1 (ascending window, accumulate)
    {
        const int accb = 129 * ((tid + 1) & 31);
        #pragma unroll 1
        for (int m = 0; m < 7; ++m) {
            const float* ipt = in_s + inb + 139 + 16 * m;     // 128+10+c(1)
            float*       apt = acc_s + accb + 16 * m;
            const float* wq  = win_s + 128 + 16 * m;
            PREFETCH(35 + 4 * (m + 1))
            FILL_X(0) FILL_W_A() FILL_A()
            ROTATE()
            RUN16_ACC()
        }
        {   // m = 7
            const float* ipt = in_s + inb + 251;              // 128+122+1
            float*       apt = acc_s + accb + 112;
            const float* wq  = win_s + 240;
            PREFETCH(67)
            FILL_X(1) FILL_W_A() FILL_A()
            ROTATE()
            RUN16_ACC()
        }
        __syncwarp();
        RETIRE_EARLY(1)
        __syncwarp();
    }

    // ---- Chunks 2,3 (mirrored window: w(j) = win_s[512-j], accumulate)
    #pragma unroll 1
    for (int c = 2; c < 4; ++c) {
        const int accb = 129 * ((tid + c) & 31);
        #pragma unroll 1
        for (int m = 0; m < 7; ++m) {
            const float* ipt = in_s + inb + 128 * c + 10 + c + 16 * m;
            float*       apt = acc_s + accb + 16 * m;
            const float* wq  = win_s + (512 - 128 * c) - 16 * m - 15;
            PREFETCH(3 + 32 * c + 4 * (m + 1))
            FILL_X(0) FILL_W_D() FILL_A()
            ROTATE()
            RUN16_ACC()
        }
        if (c == 2) {   // m = 7, row-crossing bump
            const float* ipt = in_s + inb + 380;              // 256+122+2
            float*       apt = acc_s + accb + 112;
            const float* wq  = win_s + 256 - 112 - 15;        // 129
            PREFETCH(99)
            FILL_X(1) FILL_W_D() FILL_A()
            ROTATE()
            RUN16_ACC()
            __syncwarp();
            RETIRE_EARLY(2)
            __syncwarp();
        } else {        // c == 3, m = 7: drain (t = 506..521; x=0 for t>=512)
            const float* ipt = in_s + inb + 509;              // 384+122+3
            float*       apt = acc_s + accb + 112;
            const float* wq  = win_s + 128 - 112 - 15;        // 1
            FILL_X_DRAIN() FILL_W_D() FILL_A()
            RUN16_ACC()
            __syncwarp();
        }
    }

    // ---- Phase C: retire remaining rows 3..34.
    #pragma unroll 1
    for (int B = 3; B < 35; ++B) {
        const int sb = 129 * (B & 31);
        #pragma unroll
        for (int k2 = 0; k2 < 4; ++k2) {
            int j = tid + 32 * k2;
            float v = acc_s[sb + j];
            int p = 128 * B + j;
            int u = S0 + p - PADW;
            if (B < 32) {
                outb[u] = v * 0.5f;                        // interior, norm==2
            } else if (blk != BLK_PER_B - 1) {
                atomicAdd(outb + u, v * 0.5f);             // right halo
            } else {
                if (u < NT) outb[u] = v / norm_at(S0 + p); // batch right edge
            }
        }
    }
}

extern "C" void kernel_launch(void* const* d_in, const int* in_sizes, int n_in,
                              void* d_out, int out_size) {
    const float* ex   = (const float*)d_in[0];   // (32, 131072) f32
    const float* gain = (const float*)d_in[1];   // (32, 1024)   f32
    const float* bq   = (const float*)d_in[2];   // (32, 1024, 11, 3) f32
    float* out = (float*)d_out;                  // (32, 131072) f32

    cudaFuncSetAttribute(synth_kernel, cudaFuncAttributeMaxDynamicSharedMemorySize,
                         (int)SMEM_BYTES);

    halo_zero_kernel<<<dim3(BLK_PER_B - 1, NB), 384>>>(out);
    synth_kernel<<<dim3(BLK_PER_B, NB), NFB, SMEM_BYTES>>>(ex, gain, bq, out);
}